// round 15
// baseline (speedup 1.0000x reference)
#include <cuda_runtime.h>
#include <cuda_fp16.h>
#include <mma.h>

using namespace nvcuda;

// ---------------------------------------------------------------------------
// MultiGAT: 2-layer GAT on GB300.
// - GEMMs on fp16 tensor cores (wmma HMMA, fp32 accumulate); alpha logits
//   fused into GEMM epilogues from the pre-rounding fp32 accumulators.
// - Features h1/h2 stored fp16; agg1 emits ELU(agg+b1) in fp16 so GEMM2's A
//   tile is a straight copy.
// - agg1 is ISSUE-bound (ncu R13: alu 39% dominant): single packed
//   (src|alpha_fp16) shuffle per edge (alpha was already fp16 in the HFMA2 —
//   numerically identical), guard-free gathers via alpha=0 padding, and
//   2x-unrolled edge loop. agg2 keeps fp32 alpha, gets guard removal only.
// - CSR gather-aggregate (uint16 src ids), no float atomics; softmax
//   max-shift omitted (mathematically identical ratio, values bounded).
// - edge_index dtype (int32 vs int64) detected by inline 32-byte probe.
// - 6-kernel chain: fat1(GEMM1+alpha1 ∥ hist) -> lookback-scan -> scatter ->
//   agg1 -> gemm2(+alpha2) -> agg2. Self-cleaning scratch for graph replay.
// ---------------------------------------------------------------------------

#define N_NODES 50000
#define NE      800000
#define ET      850000                    // NE + N_NODES self loops
#define GEMM_BLOCKS ((N_NODES + 127) / 128)     // 391
#define SBLK        ((N_NODES + 511) / 512)     // 98 scan blocks (512 thr)
#define DEC_BLOCKS  320                          // hist blocks appended to GEMM1

// -------- scratch (device globals; allocation-free) --------
__device__ __align__(16) __half g_h1h [N_NODES * 128];
__device__ __align__(16) __half g_agg1h[N_NODES * 128];   // ELU(agg1+b1), fp16
__device__ __align__(16) __half g_h2h [N_NODES * 64];
__device__ float g_nas1[N_NODES * 8];
__device__ float g_nad1[N_NODES * 8];
__device__ float g_nas2[N_NODES];
__device__ float g_nad2[N_NODES];
__device__ unsigned short g_esrc[ET];   // CSR: src per slot (node id < 65536)
__device__ int   g_rowptr[N_NODES + 1];
__device__ int   g_woff[N_NODES];
__device__ int   g_cnt [N_NODES];       // zeroed at load; re-zeroed by scan_k
__device__ unsigned int g_scan[SBLK];   // packed lookback word; reset by scatter_k

__device__ __forceinline__ float eluf(float v) {
    return v > 0.f ? v : expm1f(v);
}

// -------- dtype probe: int64 iff the first 8 high words are all zero --------
__device__ __forceinline__ int probe64(const void* ei) {
    const int2* p = (const int2*)ei;
    int ok = 1;
#pragma unroll
    for (int i = 0; i < 8; i++) ok &= (p[i].y == 0);
    return ok;
}

// -------- decode helpers --------
__device__ __forceinline__ int edge_dst(const void* ei, int e, int is64) {
    if (e >= NE) return e - NE;
    return is64 ? (int)((const long long*)ei)[NE + e] : ((const int*)ei)[NE + e];
}
__device__ __forceinline__ int edge_src(const void* ei, int e, int is64) {
    if (e >= NE) return e - NE;
    return is64 ? (int)((const long long*)ei)[e] : ((const int*)ei)[e];
}

// convert 8 fp32 (two float4) -> 16 halves into dst (16B-aligned)
__device__ __forceinline__ void cvt16(const float4 a, const float4 b,
                                      const float4 c, const float4 d,
                                      __half* dst) {
    __half2 h[8];
    h[0] = __floats2half2_rn(a.x, a.y); h[1] = __floats2half2_rn(a.z, a.w);
    h[2] = __floats2half2_rn(b.x, b.y); h[3] = __floats2half2_rn(b.z, b.w);
    h[4] = __floats2half2_rn(c.x, c.y); h[5] = __floats2half2_rn(c.z, c.w);
    h[6] = __floats2half2_rn(d.x, d.y); h[7] = __floats2half2_rn(d.z, d.w);
    ((uint4*)dst)[0] = ((uint4*)h)[0];
    ((uint4*)dst)[1] = ((uint4*)h)[1];
}

// ===========================================================================
// fat kernel 1: wmma GEMM1 (x@W1 -> fp16 h1 + alpha1) blocks + histogram
// ===========================================================================
#define AS_LD  80                         // half ld, As[128][80]
#define BS1_LD 136                        // half ld, Bs[64][136]
#define ST_LD  36                         // float ld, stage[128][36]

__global__ __launch_bounds__(256)
void fat1_k(const float* __restrict__ x, const float* __restrict__ W1,
            const float* __restrict__ as1, const float* __restrict__ ad1,
            const void* __restrict__ ei) {
    __shared__ __align__(16) char smem_raw[128 * AS_LD * 2 + 64 * BS1_LD * 2];
    if (blockIdx.x >= GEMM_BLOCKS) {
        const int is64 = probe64(ei);
        const int b = blockIdx.x - GEMM_BLOCKS;
        for (int e = b * 256 + threadIdx.x; e < ET; e += DEC_BLOCKS * 256)
            atomicAdd(&g_cnt[edge_dst(ei, e, is64)], 1);
        return;
    }
    __half* As = (__half*)smem_raw;                         // [128][AS_LD]
    __half* Bs = (__half*)(smem_raw + 128 * AS_LD * 2);     // [64][BS1_LD]
    float* stage = (float*)smem_raw;                        // [128][ST_LD] (reuse As)

    const int tid = threadIdx.x;
    const int wid = tid >> 5;
    const int wm = wid & 3, wn = wid >> 2;
    const int rowBase = blockIdx.x * 128;

    wmma::fragment<wmma::accumulator, 16, 16, 16, float> acc[2][4];
#pragma unroll
    for (int i = 0; i < 2; i++)
#pragma unroll
        for (int j = 0; j < 4; j++) wmma::fill_fragment(acc[i][j], 0.f);

    for (int kh = 0; kh < 2; kh++) {
        // A tile: 128 rows x 64 k (fp32 -> fp16)
        {
            const int r = tid >> 1, seg = tid & 1;
            const int row = rowBase + r;
            float4 v[8];
            if (row < N_NODES) {
                const float4* xp = (const float4*)(x + row * 128 + kh * 64 + seg * 32);
#pragma unroll
                for (int i = 0; i < 8; i++) v[i] = xp[i];
            } else {
#pragma unroll
                for (int i = 0; i < 8; i++) v[i] = make_float4(0.f, 0.f, 0.f, 0.f);
            }
            __half* dst = As + r * AS_LD + seg * 32;
            cvt16(v[0], v[1], v[2], v[3], dst);
            cvt16(v[4], v[5], v[6], v[7], dst + 16);
        }
        // B tile: 64 k x 128 n (fp32 -> fp16)
        {
            const int kk = tid >> 2, seg = tid & 3;
            const float4* wp = (const float4*)(W1 + (kh * 64 + kk) * 128 + seg * 32);
            float4 v[8];
#pragma unroll
            for (int i = 0; i < 8; i++) v[i] = wp[i];
            __half* dst = Bs + kk * BS1_LD + seg * 32;
            cvt16(v[0], v[1], v[2], v[3], dst);
            cvt16(v[4], v[5], v[6], v[7], dst + 16);
        }
        __syncthreads();
#pragma unroll
        for (int k8 = 0; k8 < 4; k8++) {
            wmma::fragment<wmma::matrix_a, 16, 16, 16, __half, wmma::row_major> af[2];
#pragma unroll
            for (int mi = 0; mi < 2; mi++)
                wmma::load_matrix_sync(af[mi], As + (wm * 32 + mi * 16) * AS_LD + k8 * 16, AS_LD);
#pragma unroll
            for (int nj = 0; nj < 4; nj++) {
                wmma::fragment<wmma::matrix_b, 16, 16, 16, __half, wmma::row_major> bf;
                wmma::load_matrix_sync(bf, Bs + (k8 * 16) * BS1_LD + wn * 64 + nj * 16, BS1_LD);
#pragma unroll
                for (int mi = 0; mi < 2; mi++)
                    wmma::mma_sync(acc[mi][nj], af[mi], bf, acc[mi][nj]);
            }
        }
        __syncthreads();
    }

    // epilogue: 4 column-quarters (32 cols each) staged through fp32 smem
    for (int q = 0; q < 4; q++) {
        if (wn == (q >> 1)) {
            const int njb = (q & 1) * 2;
#pragma unroll
            for (int mi = 0; mi < 2; mi++)
#pragma unroll
                for (int j = 0; j < 2; j++)
                    wmma::store_matrix_sync(stage + (wm * 32 + mi * 16) * ST_LD + j * 16,
                                            acc[mi][njb + j], ST_LD, wmma::mem_row_major);
        }
        __syncthreads();
        {
            const int r = tid >> 1, hf = tid & 1;
            const int row = rowBase + r;
            if (row < N_NODES) {
                const float* sp = stage + r * ST_LD + hf * 16;
                __half2 h[8];
#pragma unroll
                for (int i = 0; i < 8; i++)
                    h[i] = __floats2half2_rn(sp[2 * i], sp[2 * i + 1]);
                __half* dst = g_h1h + row * 128 + q * 32 + hf * 16;
                ((uint4*)dst)[0] = ((uint4*)h)[0];
                ((uint4*)dst)[1] = ((uint4*)h)[1];
                const int head = q * 2 + hf;
                float s = 0.f, d = 0.f;
#pragma unroll
                for (int c = 0; c < 16; c++) {
                    s += sp[c] * as1[head * 16 + c];
                    d += sp[c] * ad1[head * 16 + c];
                }
                g_nas1[row * 8 + head] = s;
                g_nad1[row * 8 + head] = d;
            }
        }
        __syncthreads();
    }
}

// ===========================================================================
// decoupled-lookback scan (unsigned status words): g_cnt -> rowptr/woff
// ===========================================================================
__global__ void scan_k() {
    __shared__ int wpre[16];
    __shared__ int sbase;
    const int t = threadIdx.x;                 // 512 threads
    const int lane = t & 31, w = t >> 5;
    const int b = blockIdx.x;
    const int i = b * 512 + t;
    int v = (i < N_NODES) ? g_cnt[i] : 0;
    int inc = v;
#pragma unroll
    for (int o = 1; o < 32; o <<= 1) {
        int u = __shfl_up_sync(0xFFFFFFFFu, inc, o);
        if (lane >= o) inc += u;
    }
    if (lane == 31) wpre[w] = inc;
    __syncthreads();
    if (t == 0) {
        int run = 0;
#pragma unroll
        for (int k = 0; k < 16; k++) { int u = wpre[k]; wpre[k] = run; run += u; }
        int base = 0;
        if (b == 0) {
            atomicExch(&g_scan[0], (2u << 30) | (unsigned)run);
        } else {
            atomicExch(&g_scan[b], (1u << 30) | (unsigned)run);  // publish aggregate
            int idx = b - 1;
            while (true) {
                unsigned int word;
                do { word = atomicAdd(&g_scan[idx], 0u); } while ((word >> 30) == 0u);
                base += (int)(word & 0x3FFFFFFFu);
                if ((word >> 30) == 2u) break;
                idx--;
            }
            atomicExch(&g_scan[b], (2u << 30) | (unsigned)(base + run));  // prefix
        }
        sbase = base;
    }
    __syncthreads();
    if (i < N_NODES) {
        const int ex = inc - v + wpre[w] + sbase;
        g_rowptr[i] = ex;
        g_woff[i]   = ex;
        g_cnt[i]    = 0;                        // ready for next replay
    }
    if (b == 0 && t == 0) g_rowptr[N_NODES] = ET;
}

// -------- scatter edges into CSR slots; resets lookback words --------
__global__ void scatter_k(const void* __restrict__ ei) {
    int e = blockIdx.x * blockDim.x + threadIdx.x;
    if (e < SBLK) g_scan[e] = 0u;
    if (e >= ET) return;
    const int is64 = probe64(ei);
    const int d = edge_dst(ei, e, is64);
    const int s = edge_src(ei, e, is64);
    int slot = atomicAdd(&g_woff[d], 1);
    g_esrc[slot] = (unsigned short)s;
}

// -------- layer-1 aggregate: warp/node, fp16 gather, 4 edges/iter;
//          single packed (src|alpha_fp16) shuffle; guard-free gathers
//          (alpha=0 padding); HFMA2 accumulation; emits ELU(acc/den+b1) fp16 -
__global__ void agg1_k(const float* __restrict__ b1) {
    const int warp = (blockIdx.x * blockDim.x + threadIdx.x) >> 5;
    const int lane = threadIdx.x & 31;
    if (warp >= N_NODES) return;
    const int n = warp;
    const int rs = g_rowptr[n], re = g_rowptr[n + 1];
    const int ql  = lane & 15;         // channel group: owns channels ql*8..ql*8+7
    const int grp = lane >> 4;         // half-warp id (edge selector)
    const int hq  = ql >> 1;           // head of this lane's channels
    const float nadh = g_nad1[n * 8 + (lane & 7)];
    float den = 0.f;
    __half2 hacc[4];
#pragma unroll
    for (int k = 0; k < 4; k++) hacc[k] = __float2half2_rn(0.f);

#pragma unroll 2
    for (int j = rs; j < re; j += 4) {
        const int eidx = j + (lane >> 3);   // lanes 8e..8e+7 handle edge j+e
        int srcg = 0;
        float ev = 0.f;
        if (eidx < re) {
            srcg = g_esrc[eidx];
            float v = g_nas1[srcg * 8 + (lane & 7)] + nadh;
            v = v > 0.f ? v : 0.2f * v;
            ev = __expf(v);
        }
        den += ev;
        // pack (src:u16 high | alpha:fp16 low); alpha was already fp16 in the
        // FMA before this change -> numerically identical
        const unsigned pw = ((unsigned)srcg << 16) |
                            (unsigned)__half_as_ushort(__float2half_rn(ev));
#pragma unroll
        for (int t = 0; t < 2; t++) {
            const int e0 = t * 2 + grp;     // this half-warp's edge this step
            const unsigned w = __shfl_sync(0xFFFFFFFFu, pw, e0 * 8 + hq);
            const int src = (int)(w >> 16);
            const __half2 a2 = __half2half2(__ushort_as_half((unsigned short)(w & 0xFFFFu)));
            // unconditional gather: OOB edges have a2 == 0 (adds zero)
            uint4 raw = ((const uint4*)g_h1h)[src * 16 + ql];
            const __half2* h2p = (const __half2*)&raw;
#pragma unroll
            for (int k = 0; k < 4; k++)
                hacc[k] = __hfma2(h2p[k], a2, hacc[k]);
        }
    }
    // unpack to fp32 and combine the two half-warps' accumulators
    float accv[8];
#pragma unroll
    for (int k = 0; k < 4; k++) {
        float2 f = __half22float2(hacc[k]);
        accv[2*k]   = f.x;
        accv[2*k+1] = f.y;
    }
#pragma unroll
    for (int k = 0; k < 8; k++)
        accv[k] += __shfl_xor_sync(0xFFFFFFFFu, accv[k], 16);
    // per-head denom: partials for head h live in lanes {h, h+8, h+16, h+24}
    den += __shfl_xor_sync(0xFFFFFFFFu, den, 8);
    den += __shfl_xor_sync(0xFFFFFFFFu, den, 16);
    const float dh = __shfl_sync(0xFFFFFFFFu, den, hq);
    const float inv = 1.f / (dh + 1e-16f);
    if (grp == 0) {
        const float4 b0 = ((const float4*)b1)[ql * 2];
        const float4 b1v = ((const float4*)b1)[ql * 2 + 1];
        float o[8];
        o[0] = eluf(accv[0]*inv + b0.x); o[1] = eluf(accv[1]*inv + b0.y);
        o[2] = eluf(accv[2]*inv + b0.z); o[3] = eluf(accv[3]*inv + b0.w);
        o[4] = eluf(accv[4]*inv + b1v.x); o[5] = eluf(accv[5]*inv + b1v.y);
        o[6] = eluf(accv[6]*inv + b1v.z); o[7] = eluf(accv[7]*inv + b1v.w);
        __half2 h[4];
#pragma unroll
        for (int k = 0; k < 4; k++) h[k] = __floats2half2_rn(o[2*k], o[2*k+1]);
        ((uint4*)(g_agg1h + n * 128 + ql * 8))[0] = *(uint4*)h;
    }
}

// ===========================================================================
// wmma GEMM2: agg1h(fp16, already ELU(agg+b1)) @ W2 -> fp16 h2 + alpha2 fused
// ===========================================================================
#define BS2_LD 80                         // half ld, Bs[64][80]

__global__ __launch_bounds__(256)
void gemm2_k(const float* __restrict__ W2,
             const float* __restrict__ as2, const float* __restrict__ ad2) {
    __shared__ __align__(16) char smem_raw[128 * AS_LD * 2 + 64 * BS2_LD * 2];
    __half* As = (__half*)smem_raw;                         // [128][AS_LD]
    __half* Bs = (__half*)(smem_raw + 128 * AS_LD * 2);     // [64][BS2_LD]
    float* stage = (float*)smem_raw;                        // [128][ST_LD]

    const int tid = threadIdx.x;
    const int wid = tid >> 5;
    const int wm = wid & 3, wn = wid >> 2;
    const int rowBase = blockIdx.x * 128;

    wmma::fragment<wmma::accumulator, 16, 16, 16, float> acc[2][2];
#pragma unroll
    for (int i = 0; i < 2; i++)
#pragma unroll
        for (int j = 0; j < 2; j++) wmma::fill_fragment(acc[i][j], 0.f);

    for (int kh = 0; kh < 2; kh++) {
        // A tile: straight fp16 copy from g_agg1h
        {
            const int r = tid >> 1, seg = tid & 1;
            const int row = rowBase + r;
            uint4 v[4];
            if (row < N_NODES) {
                const uint4* ap = (const uint4*)(g_agg1h + row * 128 + kh * 64 + seg * 32);
#pragma unroll
                for (int i = 0; i < 4; i++) v[i] = ap[i];
            } else {
#pragma unroll
                for (int i = 0; i < 4; i++) v[i] = make_uint4(0u, 0u, 0u, 0u);
            }
            uint4* dst = (uint4*)(As + r * AS_LD + seg * 32);
#pragma unroll
            for (int i = 0; i < 4; i++) dst[i] = v[i];
        }
        // B tile: 64 k x 64 n (fp32 -> fp16)
        {
            const int kk = tid >> 2, seg = tid & 3;
            const float4* wp = (const float4*)(W2 + (kh * 64 + kk) * 64 + seg * 16);
            float4 v[4];
#pragma unroll
            for (int i = 0; i < 4; i++) v[i] = wp[i];
            __half* dst = Bs + kk * BS2_LD + seg * 16;
            cvt16(v[0], v[1], v[2], v[3], dst);
        }
        __syncthreads();
#pragma unroll
        for (int k8 = 0; k8 < 4; k8++) {
            wmma::fragment<wmma::matrix_a, 16, 16, 16, __half, wmma::row_major> af[2];
#pragma unroll
            for (int mi = 0; mi < 2; mi++)
                wmma::load_matrix_sync(af[mi], As + (wm * 32 + mi * 16) * AS_LD + k8 * 16, AS_LD);
#pragma unroll
            for (int nj = 0; nj < 2; nj++) {
                wmma::fragment<wmma::matrix_b, 16, 16, 16, __half, wmma::row_major> bf;
                wmma::load_matrix_sync(bf, Bs + (k8 * 16) * BS2_LD + wn * 32 + nj * 16, BS2_LD);
#pragma unroll
                for (int mi = 0; mi < 2; mi++)
                    wmma::mma_sync(acc[mi][nj], af[mi], bf, acc[mi][nj]);
            }
        }
        __syncthreads();
    }

    // epilogue: 2 column-quarters (32 cols each); alpha2 accumulated across both
    float s2 = 0.f, d2 = 0.f;                 // owned by threads tid<128 (row = tid)
    for (int q = 0; q < 2; q++) {
        if (wn == q) {
#pragma unroll
            for (int mi = 0; mi < 2; mi++)
#pragma unroll
                for (int j = 0; j < 2; j++)
                    wmma::store_matrix_sync(stage + (wm * 32 + mi * 16) * ST_LD + j * 16,
                                            acc[mi][j], ST_LD, wmma::mem_row_major);
        }
        __syncthreads();
        {
            const int r = tid >> 1, hf = tid & 1;
            const int row = rowBase + r;
            if (row < N_NODES) {
                const float* sp = stage + r * ST_LD + hf * 16;
                __half2 h[8];
#pragma unroll
                for (int i = 0; i < 8; i++)
                    h[i] = __floats2half2_rn(sp[2 * i], sp[2 * i + 1]);
                __half* dst = g_h2h + row * 64 + q * 32 + hf * 16;
                ((uint4*)dst)[0] = ((uint4*)h)[0];
                ((uint4*)dst)[1] = ((uint4*)h)[1];
            }
        }
        if (tid < 128) {
            const int row = rowBase + tid;
            if (row < N_NODES) {
                const float* sp = stage + tid * ST_LD;
#pragma unroll
                for (int c = 0; c < 32; c++) {
                    s2 += sp[c] * as2[q * 32 + c];
                    d2 += sp[c] * ad2[q * 32 + c];
                }
            }
        }
        __syncthreads();
    }
    if (tid < 128) {
        const int row = rowBase + tid;
        if (row < N_NODES) {
            g_nas2[row] = s2;
            g_nad2[row] = d2;
        }
    }
}

// -------- layer-2 aggregate + bias + log_softmax: warp/node, 4 edges/iter;
//          guard-free gathers (alpha=0 padding); fp32 accumulation --------
__global__ void agg2_k(float* __restrict__ out, const float* __restrict__ b2) {
    const int warp = (blockIdx.x * blockDim.x + threadIdx.x) >> 5;
    const int lane = threadIdx.x & 31;
    if (warp >= N_NODES) return;
    const int n = warp;
    const int rs = g_rowptr[n], re = g_rowptr[n + 1];
    const int ql  = lane & 7;          // channel group: owns channels ql*8..ql*8+7
    const int grp = lane >> 3;         // quarter-warp id (edge selector, 0..3)
    const float nad = g_nad2[n];
    float den = 0.f;
    float accv[8];
#pragma unroll
    for (int k = 0; k < 8; k++) accv[k] = 0.f;

    for (int j = rs; j < re; j += 4) {
        const int idx = j + lane;
        int srcl = 0;
        float ev = 0.f;
        if (lane < 4 && idx < re) {
            srcl = g_esrc[idx];
            float v = g_nas2[srcl] + nad;
            v = v > 0.f ? v : 0.2f * v;
            ev = __expf(v);
            den += ev;
        }
        // each quarter-warp handles edge j+grp; shuffles unconditional
        const int   src = __shfl_sync(0xFFFFFFFFu, srcl, grp);
        const float a   = __shfl_sync(0xFFFFFFFFu, ev,   grp);
        // unconditional gather: OOB edges carry a == 0 (adds zero)
        uint4 raw = ((const uint4*)g_h2h)[src * 8 + ql];
        const __half2* h2p = (const __half2*)&raw;
#pragma unroll
        for (int k = 0; k < 4; k++) {
            float2 f = __half22float2(h2p[k]);
            accv[2*k]   += f.x * a;
            accv[2*k+1] += f.y * a;
        }
    }
    // combine the four quarter-warps' accumulators
#pragma unroll
    for (int k = 0; k < 8; k++) {
        accv[k] += __shfl_xor_sync(0xFFFFFFFFu, accv[k], 8);
        accv[k] += __shfl_xor_sync(0xFFFFFFFFu, accv[k], 16);
    }
    // denom partials live in lanes 0..3
    den += __shfl_xor_sync(0xFFFFFFFFu, den, 1);
    den += __shfl_xor_sync(0xFFFFFFFFu, den, 2);
    den  = __shfl_sync(0xFFFFFFFFu, den, 0);
    const float inv = 1.f / (den + 1e-16f);
    float v[8];
    {
        const float4 b0 = ((const float4*)b2)[ql * 2];
        const float4 b1v = ((const float4*)b2)[ql * 2 + 1];
        v[0] = accv[0]*inv + b0.x; v[1] = accv[1]*inv + b0.y;
        v[2] = accv[2]*inv + b0.z; v[3] = accv[3]*inv + b0.w;
        v[4] = accv[4]*inv + b1v.x; v[5] = accv[5]*inv + b1v.y;
        v[6] = accv[6]*inv + b1v.z; v[7] = accv[7]*inv + b1v.w;
    }
    // log_softmax over the 64 row values (8 lanes x 8 values, groups identical)
    float mx = v[0];
#pragma unroll
    for (int k = 1; k < 8; k++) mx = fmaxf(mx, v[k]);
#pragma unroll
    for (int o = 1; o < 8; o <<= 1)
        mx = fmaxf(mx, __shfl_xor_sync(0xFFFFFFFFu, mx, o));
    float s = 0.f;
#pragma unroll
    for (int k = 0; k < 8; k++) s += expf(v[k] - mx);
#pragma unroll
    for (int o = 1; o < 8; o <<= 1)
        s += __shfl_xor_sync(0xFFFFFFFFu, s, o);
    const float lse = logf(s) + mx;
    if (grp == 0) {
        float4 o0 = make_float4(v[0]-lse, v[1]-lse, v[2]-lse, v[3]-lse);
        float4 o1 = make_float4(v[4]-lse, v[5]-lse, v[6]-lse, v[7]-lse);
        ((float4*)out)[n * 16 + ql * 2]     = o0;
        ((float4*)out)[n * 16 + ql * 2 + 1] = o1;
    }
}

extern "C" void kernel_launch(void* const* d_in, const int* in_sizes, int n_in,
                              void* d_out, int out_size) {
    const float* x   = (const float*)d_in[0];
    const void*  ei  = d_in[1];                 // int32 or int64, probed inline
    const float* W1  = (const float*)d_in[2];
    const float* as1 = (const float*)d_in[3];
    const float* ad1 = (const float*)d_in[4];
    const float* b1  = (const float*)d_in[5];
    const float* W2  = (const float*)d_in[6];
    const float* as2 = (const float*)d_in[7];
    const float* ad2 = (const float*)d_in[8];
    const float* b2  = (const float*)d_in[9];
    float* out = (float*)d_out;

    const int warp_blocks = (N_NODES * 32 + 255) / 256;   // 6250

    fat1_k<<<GEMM_BLOCKS + DEC_BLOCKS, 256>>>(x, W1, as1, ad1, ei);  // GEMM1+alpha1 ∥ hist
    scan_k<<<SBLK, 512>>>();                                          // lookback scan
    scatter_k<<<(ET + 511) / 512, 512>>>(ei);
    agg1_k<<<warp_blocks, 256>>>(b1);
    gemm2_k<<<GEMM_BLOCKS, 256>>>(W2, as2, ad2);                      // GEMM2+alpha2
    agg2_k<<<warp_blocks, 256>>>(out, b2);
}

// round 16
// speedup vs baseline: 1.4523x; 1.4523x over previous
#include <cuda_runtime.h>
#include <cuda_fp16.h>
#include <mma.h>

using namespace nvcuda;

// ---------------------------------------------------------------------------
// MultiGAT: 2-layer GAT on GB300.  (R13 structure restored after R14 regression:
// packed src|alpha shuffle made gather ADDRESSES depend on __expf -> MUFU
// latency serialized into the gather path; guard-free tail gathers added L2
// hotspot traffic. Kept: separate src shuffle (expf-independent addresses),
// warp-uniform guards. New vs R13: ev converted to fp16 BEFORE the alpha
// shuffle (one F2H per lane per iter instead of one per t-step; numerically
// identical quantization point).)
// - GEMMs on fp16 tensor cores (wmma HMMA, fp32 accumulate); alpha logits
//   fused into GEMM epilogues from the pre-rounding fp32 accumulators.
// - Features h1/h2 stored fp16; agg1 emits ELU(agg+b1) in fp16 so GEMM2's A
//   tile is a straight copy. agg1 accumulates in HFMA2 (issue-bound kernel;
//   errors attenuate ~50x downstream, measured R8->R9). agg2 stays fp32.
// - CSR gather-aggregate (uint16 src ids), no float atomics; softmax
//   max-shift omitted (mathematically identical ratio, values bounded).
// - edge_index dtype (int32 vs int64) detected by inline 32-byte probe.
// - 6-kernel chain: fat1(GEMM1+alpha1 ∥ hist) -> lookback-scan -> scatter ->
//   agg1 -> gemm2(+alpha2) -> agg2. Self-cleaning scratch for graph replay.
// ---------------------------------------------------------------------------

#define N_NODES 50000
#define NE      800000
#define ET      850000                    // NE + N_NODES self loops
#define GEMM_BLOCKS ((N_NODES + 127) / 128)     // 391
#define SBLK        ((N_NODES + 511) / 512)     // 98 scan blocks (512 thr)
#define DEC_BLOCKS  320                          // hist blocks appended to GEMM1

// -------- scratch (device globals; allocation-free) --------
__device__ __align__(16) __half g_h1h [N_NODES * 128];
__device__ __align__(16) __half g_agg1h[N_NODES * 128];   // ELU(agg1+b1), fp16
__device__ __align__(16) __half g_h2h [N_NODES * 64];
__device__ float g_nas1[N_NODES * 8];
__device__ float g_nad1[N_NODES * 8];
__device__ float g_nas2[N_NODES];
__device__ float g_nad2[N_NODES];
__device__ unsigned short g_esrc[ET];   // CSR: src per slot (node id < 65536)
__device__ int   g_rowptr[N_NODES + 1];
__device__ int   g_woff[N_NODES];
__device__ int   g_cnt [N_NODES];       // zeroed at load; re-zeroed by scan_k
__device__ unsigned int g_scan[SBLK];   // packed lookback word; reset by scatter_k

__device__ __forceinline__ float eluf(float v) {
    return v > 0.f ? v : expm1f(v);
}

// -------- dtype probe: int64 iff the first 8 high words are all zero --------
__device__ __forceinline__ int probe64(const void* ei) {
    const int2* p = (const int2*)ei;
    int ok = 1;
#pragma unroll
    for (int i = 0; i < 8; i++) ok &= (p[i].y == 0);
    return ok;
}

// -------- decode helpers --------
__device__ __forceinline__ int edge_dst(const void* ei, int e, int is64) {
    if (e >= NE) return e - NE;
    return is64 ? (int)((const long long*)ei)[NE + e] : ((const int*)ei)[NE + e];
}
__device__ __forceinline__ int edge_src(const void* ei, int e, int is64) {
    if (e >= NE) return e - NE;
    return is64 ? (int)((const long long*)ei)[e] : ((const int*)ei)[e];
}

// convert 8 fp32 (two float4) -> 16 halves into dst (16B-aligned)
__device__ __forceinline__ void cvt16(const float4 a, const float4 b,
                                      const float4 c, const float4 d,
                                      __half* dst) {
    __half2 h[8];
    h[0] = __floats2half2_rn(a.x, a.y); h[1] = __floats2half2_rn(a.z, a.w);
    h[2] = __floats2half2_rn(b.x, b.y); h[3] = __floats2half2_rn(b.z, b.w);
    h[4] = __floats2half2_rn(c.x, c.y); h[5] = __floats2half2_rn(c.z, c.w);
    h[6] = __floats2half2_rn(d.x, d.y); h[7] = __floats2half2_rn(d.z, d.w);
    ((uint4*)dst)[0] = ((uint4*)h)[0];
    ((uint4*)dst)[1] = ((uint4*)h)[1];
}

// ===========================================================================
// fat kernel 1: wmma GEMM1 (x@W1 -> fp16 h1 + alpha1) blocks + histogram
// ===========================================================================
#define AS_LD  80                         // half ld, As[128][80]
#define BS1_LD 136                        // half ld, Bs[64][136]
#define ST_LD  36                         // float ld, stage[128][36]

__global__ __launch_bounds__(256)
void fat1_k(const float* __restrict__ x, const float* __restrict__ W1,
            const float* __restrict__ as1, const float* __restrict__ ad1,
            const void* __restrict__ ei) {
    __shared__ __align__(16) char smem_raw[128 * AS_LD * 2 + 64 * BS1_LD * 2];
    if (blockIdx.x >= GEMM_BLOCKS) {
        const int is64 = probe64(ei);
        const int b = blockIdx.x - GEMM_BLOCKS;
        for (int e = b * 256 + threadIdx.x; e < ET; e += DEC_BLOCKS * 256)
            atomicAdd(&g_cnt[edge_dst(ei, e, is64)], 1);
        return;
    }
    __half* As = (__half*)smem_raw;                         // [128][AS_LD]
    __half* Bs = (__half*)(smem_raw + 128 * AS_LD * 2);     // [64][BS1_LD]
    float* stage = (float*)smem_raw;                        // [128][ST_LD] (reuse As)

    const int tid = threadIdx.x;
    const int wid = tid >> 5;
    const int wm = wid & 3, wn = wid >> 2;
    const int rowBase = blockIdx.x * 128;

    wmma::fragment<wmma::accumulator, 16, 16, 16, float> acc[2][4];
#pragma unroll
    for (int i = 0; i < 2; i++)
#pragma unroll
        for (int j = 0; j < 4; j++) wmma::fill_fragment(acc[i][j], 0.f);

    for (int kh = 0; kh < 2; kh++) {
        // A tile: 128 rows x 64 k (fp32 -> fp16)
        {
            const int r = tid >> 1, seg = tid & 1;
            const int row = rowBase + r;
            float4 v[8];
            if (row < N_NODES) {
                const float4* xp = (const float4*)(x + row * 128 + kh * 64 + seg * 32);
#pragma unroll
                for (int i = 0; i < 8; i++) v[i] = xp[i];
            } else {
#pragma unroll
                for (int i = 0; i < 8; i++) v[i] = make_float4(0.f, 0.f, 0.f, 0.f);
            }
            __half* dst = As + r * AS_LD + seg * 32;
            cvt16(v[0], v[1], v[2], v[3], dst);
            cvt16(v[4], v[5], v[6], v[7], dst + 16);
        }
        // B tile: 64 k x 128 n (fp32 -> fp16)
        {
            const int kk = tid >> 2, seg = tid & 3;
            const float4* wp = (const float4*)(W1 + (kh * 64 + kk) * 128 + seg * 32);
            float4 v[8];
#pragma unroll
            for (int i = 0; i < 8; i++) v[i] = wp[i];
            __half* dst = Bs + kk * BS1_LD + seg * 32;
            cvt16(v[0], v[1], v[2], v[3], dst);
            cvt16(v[4], v[5], v[6], v[7], dst + 16);
        }
        __syncthreads();
#pragma unroll
        for (int k8 = 0; k8 < 4; k8++) {
            wmma::fragment<wmma::matrix_a, 16, 16, 16, __half, wmma::row_major> af[2];
#pragma unroll
            for (int mi = 0; mi < 2; mi++)
                wmma::load_matrix_sync(af[mi], As + (wm * 32 + mi * 16) * AS_LD + k8 * 16, AS_LD);
#pragma unroll
            for (int nj = 0; nj < 4; nj++) {
                wmma::fragment<wmma::matrix_b, 16, 16, 16, __half, wmma::row_major> bf;
                wmma::load_matrix_sync(bf, Bs + (k8 * 16) * BS1_LD + wn * 64 + nj * 16, BS1_LD);
#pragma unroll
                for (int mi = 0; mi < 2; mi++)
                    wmma::mma_sync(acc[mi][nj], af[mi], bf, acc[mi][nj]);
            }
        }
        __syncthreads();
    }

    // epilogue: 4 column-quarters (32 cols each) staged through fp32 smem
    for (int q = 0; q < 4; q++) {
        if (wn == (q >> 1)) {
            const int njb = (q & 1) * 2;
#pragma unroll
            for (int mi = 0; mi < 2; mi++)
#pragma unroll
                for (int j = 0; j < 2; j++)
                    wmma::store_matrix_sync(stage + (wm * 32 + mi * 16) * ST_LD + j * 16,
                                            acc[mi][njb + j], ST_LD, wmma::mem_row_major);
        }
        __syncthreads();
        {
            const int r = tid >> 1, hf = tid & 1;
            const int row = rowBase + r;
            if (row < N_NODES) {
                const float* sp = stage + r * ST_LD + hf * 16;
                __half2 h[8];
#pragma unroll
                for (int i = 0; i < 8; i++)
                    h[i] = __floats2half2_rn(sp[2 * i], sp[2 * i + 1]);
                __half* dst = g_h1h + row * 128 + q * 32 + hf * 16;
                ((uint4*)dst)[0] = ((uint4*)h)[0];
                ((uint4*)dst)[1] = ((uint4*)h)[1];
                const int head = q * 2 + hf;
                float s = 0.f, d = 0.f;
#pragma unroll
                for (int c = 0; c < 16; c++) {
                    s += sp[c] * as1[head * 16 + c];
                    d += sp[c] * ad1[head * 16 + c];
                }
                g_nas1[row * 8 + head] = s;
                g_nad1[row * 8 + head] = d;
            }
        }
        __syncthreads();
    }
}

// ===========================================================================
// decoupled-lookback scan (unsigned status words): g_cnt -> rowptr/woff
// ===========================================================================
__global__ void scan_k() {
    __shared__ int wpre[16];
    __shared__ int sbase;
    const int t = threadIdx.x;                 // 512 threads
    const int lane = t & 31, w = t >> 5;
    const int b = blockIdx.x;
    const int i = b * 512 + t;
    int v = (i < N_NODES) ? g_cnt[i] : 0;
    int inc = v;
#pragma unroll
    for (int o = 1; o < 32; o <<= 1) {
        int u = __shfl_up_sync(0xFFFFFFFFu, inc, o);
        if (lane >= o) inc += u;
    }
    if (lane == 31) wpre[w] = inc;
    __syncthreads();
    if (t == 0) {
        int run = 0;
#pragma unroll
        for (int k = 0; k < 16; k++) { int u = wpre[k]; wpre[k] = run; run += u; }
        int base = 0;
        if (b == 0) {
            atomicExch(&g_scan[0], (2u << 30) | (unsigned)run);
        } else {
            atomicExch(&g_scan[b], (1u << 30) | (unsigned)run);  // publish aggregate
            int idx = b - 1;
            while (true) {
                unsigned int word;
                do { word = atomicAdd(&g_scan[idx], 0u); } while ((word >> 30) == 0u);
                base += (int)(word & 0x3FFFFFFFu);
                if ((word >> 30) == 2u) break;
                idx--;
            }
            atomicExch(&g_scan[b], (2u << 30) | (unsigned)(base + run));  // prefix
        }
        sbase = base;
    }
    __syncthreads();
    if (i < N_NODES) {
        const int ex = inc - v + wpre[w] + sbase;
        g_rowptr[i] = ex;
        g_woff[i]   = ex;
        g_cnt[i]    = 0;                        // ready for next replay
    }
    if (b == 0 && t == 0) g_rowptr[N_NODES] = ET;
}

// -------- scatter edges into CSR slots; resets lookback words --------
__global__ void scatter_k(const void* __restrict__ ei) {
    int e = blockIdx.x * blockDim.x + threadIdx.x;
    if (e < SBLK) g_scan[e] = 0u;
    if (e >= ET) return;
    const int is64 = probe64(ei);
    const int d = edge_dst(ei, e, is64);
    const int s = edge_src(ei, e, is64);
    int slot = atomicAdd(&g_woff[d], 1);
    g_esrc[slot] = (unsigned short)s;
}

// -------- layer-1 aggregate: warp/node, fp16 gather, 4 edges/iter;
//          HFMA2 accumulation; src shuffle SEPARATE from alpha shuffle so
//          gather addresses never wait on __expf; ev converted to fp16 once
//          per lane before the alpha shuffle. Emits ELU(acc/den+b1) fp16. ----
__global__ void agg1_k(const float* __restrict__ b1) {
    const int warp = (blockIdx.x * blockDim.x + threadIdx.x) >> 5;
    const int lane = threadIdx.x & 31;
    if (warp >= N_NODES) return;
    const int n = warp;
    const int rs = g_rowptr[n], re = g_rowptr[n + 1];
    const int ql  = lane & 15;         // channel group: owns channels ql*8..ql*8+7
    const int grp = lane >> 4;         // half-warp id (edge selector)
    const int hq  = ql >> 1;           // head of this lane's channels
    const float nadh = g_nad1[n * 8 + (lane & 7)];
    float den = 0.f;
    __half2 hacc[4];
#pragma unroll
    for (int k = 0; k < 4; k++) hacc[k] = __float2half2_rn(0.f);

    for (int j = rs; j < re; j += 4) {
        const int eidx = j + (lane >> 3);   // lanes 8e..8e+7 handle edge j+e
        int srcg = 0;
        float ev = 0.f;
        if (eidx < re) {
            srcg = g_esrc[eidx];
            float v = g_nas1[srcg * 8 + (lane & 7)] + nadh;
            v = v > 0.f ? v : 0.2f * v;
            ev = __expf(v);
            den += ev;
        }
        // convert own ev to fp16 ONCE (quantization point identical to R13)
        const int evh = (int)__half_as_ushort(__float2half_rn(ev));
#pragma unroll
        for (int t = 0; t < 2; t++) {
            const int e0 = t * 2 + grp;     // this half-warp's edge this step
            // src shuffle independent of expf -> gather address issues early
            const int src = __shfl_sync(0xFFFFFFFFu, srcg, e0 * 8);
            const int ah  = __shfl_sync(0xFFFFFFFFu, evh,  e0 * 8 + hq);
            if (j + e0 < re) {              // warp-uniform guard
                const __half2 a2 =
                    __half2half2(__ushort_as_half((unsigned short)ah));
                uint4 raw = ((const uint4*)g_h1h)[src * 16 + ql];
                const __half2* h2p = (const __half2*)&raw;
#pragma unroll
                for (int k = 0; k < 4; k++)
                    hacc[k] = __hfma2(h2p[k], a2, hacc[k]);
            }
        }
    }
    // unpack to fp32 and combine the two half-warps' accumulators
    float accv[8];
#pragma unroll
    for (int k = 0; k < 4; k++) {
        float2 f = __half22float2(hacc[k]);
        accv[2*k]   = f.x;
        accv[2*k+1] = f.y;
    }
#pragma unroll
    for (int k = 0; k < 8; k++)
        accv[k] += __shfl_xor_sync(0xFFFFFFFFu, accv[k], 16);
    // per-head denom: partials for head h live in lanes {h, h+8, h+16, h+24}
    den += __shfl_xor_sync(0xFFFFFFFFu, den, 8);
    den += __shfl_xor_sync(0xFFFFFFFFu, den, 16);
    const float dh = __shfl_sync(0xFFFFFFFFu, den, hq);
    const float inv = 1.f / (dh + 1e-16f);
    if (grp == 0) {
        const float4 b0 = ((const float4*)b1)[ql * 2];
        const float4 b1v = ((const float4*)b1)[ql * 2 + 1];
        float o[8];
        o[0] = eluf(accv[0]*inv + b0.x); o[1] = eluf(accv[1]*inv + b0.y);
        o[2] = eluf(accv[2]*inv + b0.z); o[3] = eluf(accv[3]*inv + b0.w);
        o[4] = eluf(accv[4]*inv + b1v.x); o[5] = eluf(accv[5]*inv + b1v.y);
        o[6] = eluf(accv[6]*inv + b1v.z); o[7] = eluf(accv[7]*inv + b1v.w);
        __half2 h[4];
#pragma unroll
        for (int k = 0; k < 4; k++) h[k] = __floats2half2_rn(o[2*k], o[2*k+1]);
        ((uint4*)(g_agg1h + n * 128 + ql * 8))[0] = *(uint4*)h;
    }
}

// ===========================================================================
// wmma GEMM2: agg1h(fp16, already ELU(agg+b1)) @ W2 -> fp16 h2 + alpha2 fused
// ===========================================================================
#define BS2_LD 80                         // half ld, Bs[64][80]

__global__ __launch_bounds__(256)
void gemm2_k(const float* __restrict__ W2,
             const float* __restrict__ as2, const float* __restrict__ ad2) {
    __shared__ __align__(16) char smem_raw[128 * AS_LD * 2 + 64 * BS2_LD * 2];
    __half* As = (__half*)smem_raw;                         // [128][AS_LD]
    __half* Bs = (__half*)(smem_raw + 128 * AS_LD * 2);     // [64][BS2_LD]
    float* stage = (float*)smem_raw;                        // [128][ST_LD]

    const int tid = threadIdx.x;
    const int wid = tid >> 5;
    const int wm = wid & 3, wn = wid >> 2;
    const int rowBase = blockIdx.x * 128;

    wmma::fragment<wmma::accumulator, 16, 16, 16, float> acc[2][2];
#pragma unroll
    for (int i = 0; i < 2; i++)
#pragma unroll
        for (int j = 0; j < 2; j++) wmma::fill_fragment(acc[i][j], 0.f);

    for (int kh = 0; kh < 2; kh++) {
        // A tile: straight fp16 copy from g_agg1h
        {
            const int r = tid >> 1, seg = tid & 1;
            const int row = rowBase + r;
            uint4 v[4];
            if (row < N_NODES) {
                const uint4* ap = (const uint4*)(g_agg1h + row * 128 + kh * 64 + seg * 32);
#pragma unroll
                for (int i = 0; i < 4; i++) v[i] = ap[i];
            } else {
#pragma unroll
                for (int i = 0; i < 4; i++) v[i] = make_uint4(0u, 0u, 0u, 0u);
            }
            uint4* dst = (uint4*)(As + r * AS_LD + seg * 32);
#pragma unroll
            for (int i = 0; i < 4; i++) dst[i] = v[i];
        }
        // B tile: 64 k x 64 n (fp32 -> fp16)
        {
            const int kk = tid >> 2, seg = tid & 3;
            const float4* wp = (const float4*)(W2 + (kh * 64 + kk) * 64 + seg * 16);
            float4 v[4];
#pragma unroll
            for (int i = 0; i < 4; i++) v[i] = wp[i];
            __half* dst = Bs + kk * BS2_LD + seg * 16;
            cvt16(v[0], v[1], v[2], v[3], dst);
        }
        __syncthreads();
#pragma unroll
        for (int k8 = 0; k8 < 4; k8++) {
            wmma::fragment<wmma::matrix_a, 16, 16, 16, __half, wmma::row_major> af[2];
#pragma unroll
            for (int mi = 0; mi < 2; mi++)
                wmma::load_matrix_sync(af[mi], As + (wm * 32 + mi * 16) * AS_LD + k8 * 16, AS_LD);
#pragma unroll
            for (int nj = 0; nj < 2; nj++) {
                wmma::fragment<wmma::matrix_b, 16, 16, 16, __half, wmma::row_major> bf;
                wmma::load_matrix_sync(bf, Bs + (k8 * 16) * BS2_LD + wn * 32 + nj * 16, BS2_LD);
#pragma unroll
                for (int mi = 0; mi < 2; mi++)
                    wmma::mma_sync(acc[mi][nj], af[mi], bf, acc[mi][nj]);
            }
        }
        __syncthreads();
    }

    // epilogue: 2 column-quarters (32 cols each); alpha2 accumulated across both
    float s2 = 0.f, d2 = 0.f;                 // owned by threads tid<128 (row = tid)
    for (int q = 0; q < 2; q++) {
        if (wn == q) {
#pragma unroll
            for (int mi = 0; mi < 2; mi++)
#pragma unroll
                for (int j = 0; j < 2; j++)
                    wmma::store_matrix_sync(stage + (wm * 32 + mi * 16) * ST_LD + j * 16,
                                            acc[mi][j], ST_LD, wmma::mem_row_major);
        }
        __syncthreads();
        {
            const int r = tid >> 1, hf = tid & 1;
            const int row = rowBase + r;
            if (row < N_NODES) {
                const float* sp = stage + r * ST_LD + hf * 16;
                __half2 h[8];
#pragma unroll
                for (int i = 0; i < 8; i++)
                    h[i] = __floats2half2_rn(sp[2 * i], sp[2 * i + 1]);
                __half* dst = g_h2h + row * 64 + q * 32 + hf * 16;
                ((uint4*)dst)[0] = ((uint4*)h)[0];
                ((uint4*)dst)[1] = ((uint4*)h)[1];
            }
        }
        if (tid < 128) {
            const int row = rowBase + tid;
            if (row < N_NODES) {
                const float* sp = stage + tid * ST_LD;
#pragma unroll
                for (int c = 0; c < 32; c++) {
                    s2 += sp[c] * as2[q * 32 + c];
                    d2 += sp[c] * ad2[q * 32 + c];
                }
            }
        }
        __syncthreads();
    }
    if (tid < 128) {
        const int row = rowBase + tid;
        if (row < N_NODES) {
            g_nas2[row] = s2;
            g_nad2[row] = d2;
        }
    }
}

// -------- layer-2 aggregate + bias + log_softmax: warp/node, 4 edges/iter ----
__global__ void agg2_k(float* __restrict__ out, const float* __restrict__ b2) {
    const int warp = (blockIdx.x * blockDim.x + threadIdx.x) >> 5;
    const int lane = threadIdx.x & 31;
    if (warp >= N_NODES) return;
    const int n = warp;
    const int rs = g_rowptr[n], re = g_rowptr[n + 1];
    const int ql  = lane & 7;          // channel group: owns channels ql*8..ql*8+7
    const int grp = lane >> 3;         // quarter-warp id (edge selector, 0..3)
    const float nad = g_nad2[n];
    float den = 0.f;
    float accv[8];
#pragma unroll
    for (int k = 0; k < 8; k++) accv[k] = 0.f;

    for (int j = rs; j < re; j += 4) {
        const int idx = j + lane;
        int srcl = 0;
        float ev = 0.f;
        if (lane < 4 && idx < re) {
            srcl = g_esrc[idx];
            float v = g_nas2[srcl] + nad;
            v = v > 0.f ? v : 0.2f * v;
            ev = __expf(v);
            den += ev;
        }
        // each quarter-warp handles edge j+grp; shuffles unconditional
        const int   src = __shfl_sync(0xFFFFFFFFu, srcl, grp);
        const float a   = __shfl_sync(0xFFFFFFFFu, ev,   grp);
        if (j + grp < re) {
            uint4 raw = ((const uint4*)g_h2h)[src * 8 + ql];
            const __half2* h2p = (const __half2*)&raw;
#pragma unroll
            for (int k = 0; k < 4; k++) {
                float2 f = __half22float2(h2p[k]);
                accv[2*k]   += f.x * a;
                accv[2*k+1] += f.y * a;
            }
        }
    }
    // combine the four quarter-warps' accumulators
#pragma unroll
    for (int k = 0; k < 8; k++) {
        accv[k] += __shfl_xor_sync(0xFFFFFFFFu, accv[k], 8);
        accv[k] += __shfl_xor_sync(0xFFFFFFFFu, accv[k], 16);
    }
    // denom partials live in lanes 0..3
    den += __shfl_xor_sync(0xFFFFFFFFu, den, 1);
    den += __shfl_xor_sync(0xFFFFFFFFu, den, 2);
    den  = __shfl_sync(0xFFFFFFFFu, den, 0);
    const float inv = 1.f / (den + 1e-16f);
    float v[8];
    {
        const float4 b0 = ((const float4*)b2)[ql * 2];
        const float4 b1v = ((const float4*)b2)[ql * 2 + 1];
        v[0] = accv[0]*inv + b0.x; v[1] = accv[1]*inv + b0.y;
        v[2] = accv[2]*inv + b0.z; v[3] = accv[3]*inv + b0.w;
        v[4] = accv[4]*inv + b1v.x; v[5] = accv[5]*inv + b1v.y;
        v[6] = accv[6]*inv + b1v.z; v[7] = accv[7]*inv + b1v.w;
    }
    // log_softmax over the 64 row values (8 lanes x 8 values, groups identical)
    float mx = v[0];
#pragma unroll
    for (int k = 1; k < 8; k++) mx = fmaxf(mx, v[k]);
#pragma unroll
    for (int o = 1; o < 8; o <<= 1)
        mx = fmaxf(mx, __shfl_xor_sync(0xFFFFFFFFu, mx, o));
    float s = 0.f;
#pragma unroll
    for (int k = 0; k < 8; k++) s += expf(v[k] - mx);
#pragma unroll
    for (int o = 1; o < 8; o <<= 1)
        s += __shfl_xor_sync(0xFFFFFFFFu, s, o);
    const float lse = logf(s) + mx;
    if (grp == 0) {
        float4 o0 = make_float4(v[0]-lse, v[1]-lse, v[2]-lse, v[3]-lse);
        float4 o1 = make_float4(v[4]-lse, v[5]-lse, v[6]-lse, v[7]-lse);
        ((float4*)out)[n * 16 + ql * 2]     = o0;
        ((float4*)out)[n * 16 + ql * 2 + 1] = o1;
    }
}

extern "C" void kernel_launch(void* const* d_in, const int* in_sizes, int n_in,
                              void* d_out, int out_size) {
    const float* x   = (const float*)d_in[0];
    const void*  ei  = d_in[1];                 // int32 or int64, probed inline
    const float* W1  = (const float*)d_in[2];
    const float* as1 = (const float*)d_in[3];
    const float* ad1 = (const float*)d_in[4];
    const float* b1  = (const float*)d_in[5];
    const float* W2  = (const float*)d_in[6];
    const float* as2 = (const float*)d_in[7];
    const float* ad2 = (const float*)d_in[8];
    const float* b2  = (const float*)d_in[9];
    float* out = (float*)d_out;

    const int warp_blocks = (N_NODES * 32 + 255) / 256;   // 6250

    fat1_k<<<GEMM_BLOCKS + DEC_BLOCKS, 256>>>(x, W1, as1, ad1, ei);  // GEMM1+alpha1 ∥ hist
    scan_k<<<SBLK, 512>>>();                                          // lookback scan
    scatter_k<<<(ET + 511) / 512, 512>>>(ei);
    agg1_k<<<warp_blocks, 256>>>(b1);
    gemm2_k<<<GEMM_BLOCKS, 256>>>(W2, as2, ad2);                      // GEMM2+alpha2
    agg2_k<<<warp_blocks, 256>>>(out, b2);
}